// round 5
// baseline (speedup 1.0000x reference)
#include <cuda_runtime.h>
#include <cuda_bf16.h>

// Fused DCNv2 forward, 4 pixels/thread (2x2 quad), packed f32x2 math.
//   ow   = conv3x3(x; w_off, b_off)            -> 27 channels per pixel
//   off  = ow[0:18]  (K=9 points, (y,x) pairs)
//   mask = sigmoid(ow[18:27])
//   out[o] = b_def[o] + sum_{c,k} w_def[o,c,k] * bilinear(x[c], p_k) * mask[k]
//
// x (8,3,512,512) f32, w_off (27,3,3,3), b_off (27), w_def (3,3,3,3), b_def (3).

#define HH 512
#define WW 512
#define CC 3
#define OCC 27
#define OCP 28          // padded to even for LDS.128 pairs
#define KK 9
#define HW (HH * WW)

typedef unsigned long long u64;

__device__ __forceinline__ u64 pk2(float lo, float hi) {
    u64 r; asm("mov.b64 %0, {%1, %2};" : "=l"(r) : "f"(lo), "f"(hi)); return r;
}
__device__ __forceinline__ void upk2(u64 v, float& lo, float& hi) {
    asm("mov.b64 {%0, %1}, %2;" : "=f"(lo), "=f"(hi) : "l"(v));
}
__device__ __forceinline__ void ffma2(u64& acc, u64 a, u64 b) {
    asm("fma.rn.f32x2 %0, %1, %2, %0;" : "+l"(acc) : "l"(a), "l"(b));
}

// Deformable sampling + channel mix + store for one horizontal pixel pair
// at (hI, wI),(hI, wI+1), given its 27 packed conv outputs.
__device__ __forceinline__ void deform_store(
    const float* __restrict__ xb, int hI, int wI,
    const u64* __restrict__ ow,
    const u64* __restrict__ s_wdd, const float* __restrict__ s_bdef,
    float* __restrict__ out, size_t obase)
{
    u64 acc[3];
#pragma unroll
    for (int o = 0; o < 3; ++o) acc[o] = pk2(s_bdef[o], s_bdef[o]);

#pragma unroll
    for (int k = 0; k < KK; ++k) {
        float oy0, oy1, ox0, ox1, z0, z1;
        upk2(ow[2 * k],     oy0, oy1);
        upk2(ow[2 * k + 1], ox0, ox1);
        upk2(ow[18 + k],    z0,  z1);
        const float m0 = __fdividef(1.0f, 1.0f + __expf(-z0));
        const float m1 = __fdividef(1.0f, 1.0f + __expf(-z1));

        const float kyf = (float)(k / 3 - 1);
        const float kxf = (float)(k % 3 - 1);

        float w00[2], w01[2], w10[2], w11[2];
        int   i00[2];
        bool  y0v[2], y1v[2], x0v[2], x1v[2];
#pragma unroll
        for (int p = 0; p < 2; ++p) {
            const float py = (float)hI + kyf + (p ? oy1 : oy0);
            const float px = (float)(wI + p) + kxf + (p ? ox1 : ox0);
            const float y0f = floorf(py);
            const float x0f = floorf(px);
            const float dy = py - y0f;
            const float dx = px - x0f;
            const int y0 = (int)y0f;
            const int x0 = (int)x0f;
            w00[p] = (1.0f - dy) * (1.0f - dx);
            w01[p] = (1.0f - dy) * dx;
            w10[p] = dy * (1.0f - dx);
            w11[p] = dy * dx;
            y0v[p] = ((unsigned)y0       < (unsigned)HH);
            y1v[p] = ((unsigned)(y0 + 1) < (unsigned)HH);
            x0v[p] = ((unsigned)x0       < (unsigned)WW);
            x1v[p] = ((unsigned)(x0 + 1) < (unsigned)WW);
            i00[p] = y0 * WW + x0;
        }

#pragma unroll
        for (int c = 0; c < CC; ++c) {
            const float* pc = xb + c * HW;
            float val[2];
#pragma unroll
            for (int p = 0; p < 2; ++p) {
                const float v00 = (y0v[p] && x0v[p]) ? __ldg(pc + i00[p])          : 0.0f;
                const float v01 = (y0v[p] && x1v[p]) ? __ldg(pc + i00[p] + 1)      : 0.0f;
                const float v10 = (y1v[p] && x0v[p]) ? __ldg(pc + i00[p] + WW)     : 0.0f;
                const float v11 = (y1v[p] && x1v[p]) ? __ldg(pc + i00[p] + WW + 1) : 0.0f;
                val[p] = v00 * w00[p] + v01 * w01[p] + v10 * w10[p] + v11 * w11[p];
            }
            const u64 vp = pk2(val[0] * m0, val[1] * m1);
#pragma unroll
            for (int o = 0; o < 3; ++o)
                ffma2(acc[o], s_wdd[o * 27 + c * 9 + k], vp);
        }
    }

#pragma unroll
    for (int o = 0; o < 3; ++o) {
        float lo, hi; upk2(acc[o], lo, hi);
        *reinterpret_cast<float2*>(out + obase + (size_t)o * HW) = make_float2(lo, hi);
    }
}

__global__ __launch_bounds__(128, 3)
void dcn_fused4_kernel(const float* __restrict__ x,
                       const float* __restrict__ w_off,
                       const float* __restrict__ b_off,
                       const float* __restrict__ w_def,
                       const float* __restrict__ b_def,
                       float* __restrict__ out)
{
    // Duplicated + transposed conv weights: s_wd[g*OCP + oc] = {w[oc][g], w[oc][g]}
    __shared__ __align__(16) u64 s_wd[OCC * OCP];   // 756 * 8B
    __shared__ u64 s_wdd[3 * 27];                   // duplicated w_def
    __shared__ float s_boff[OCC];
    __shared__ float s_bdef[3];

    for (int i = threadIdx.x; i < OCC * OCP; i += blockDim.x) {
        const int g = i / OCP, oc = i % OCP;
        const float w = (oc < OCC) ? w_off[oc * 27 + g] : 0.0f;
        s_wd[i] = pk2(w, w);
    }
    for (int i = threadIdx.x; i < 3 * 27; i += blockDim.x) {
        const float w = w_def[i];
        s_wdd[i] = pk2(w, w);
    }
    if (threadIdx.x < OCC) s_boff[threadIdx.x] = b_off[threadIdx.x];
    if (threadIdx.x < 3)   s_bdef[threadIdx.x] = b_def[threadIdx.x];
    __syncthreads();

    // One thread = 2x2 quad: rows hI, hI+1; cols wI, wI+1 (hI, wI even).
    const int idx = blockIdx.x * blockDim.x + threadIdx.x;   // 0 .. 8*256*256-1
    const int wI = (idx & 255) << 1;
    const int hI = ((idx >> 8) & 255) << 1;
    const int b  = idx >> 16;

    const float* xb = x + (size_t)b * CC * HW;

    // ---- offset/mask conv on both row-pairs (packed over the 2 columns) ----
    u64 owT[OCP], owB[OCP];
#pragma unroll
    for (int oc = 0; oc < OCC; ++oc) {
        const u64 bv = pk2(s_boff[oc], s_boff[oc]);
        owT[oc] = bv; owB[oc] = bv;
    }
    owT[27] = 0ull; owB[27] = 0ull;

#pragma unroll
    for (int c = 0; c < CC; ++c) {
        const float* xc = xb + c * HW;
        // 4x4 window covering both pairs' 3x3 neighborhoods (zero padded)
        float win[16];
#pragma unroll
        for (int r = 0; r < 4; ++r) {
            const int y = hI + r - 1;
            const bool yv = ((unsigned)y < (unsigned)HH);
#pragma unroll
            for (int j = 0; j < 4; ++j) {
                const int xx = wI + j - 1;
                const bool v = yv && ((unsigned)xx < (unsigned)WW);
                win[r * 4 + j] = v ? __ldg(xc + y * WW + xx) : 0.0f;
            }
        }
#pragma unroll
        for (int t = 0; t < 9; ++t) {
            const int ky = t / 3, kx = t % 3;
            const u64 vT = pk2(win[ky * 4 + kx],       win[ky * 4 + kx + 1]);
            const u64 vB = pk2(win[(ky + 1) * 4 + kx], win[(ky + 1) * 4 + kx + 1]);
            const ulonglong2* wrow =
                reinterpret_cast<const ulonglong2*>(&s_wd[(c * 9 + t) * OCP]);
#pragma unroll
            for (int i = 0; i < OCP / 2; ++i) {      // 14 x LDS.128, each feeds 4 FFMA2
                const ulonglong2 wv = wrow[i];
                ffma2(owT[2 * i],     wv.x, vT);
                ffma2(owT[2 * i + 1], wv.y, vT);
                ffma2(owB[2 * i],     wv.x, vB);
                ffma2(owB[2 * i + 1], wv.y, vB);
            }
        }
    }

    // ---- deformable sampling + channel mix, one row-pair at a time ----
    const size_t obaseT = (size_t)b * 3 * HW + (size_t)hI * WW + wI;
    deform_store(xb, hI,     wI, owT, s_wdd, s_bdef, out, obaseT);
    deform_store(xb, hI + 1, wI, owB, s_wdd, s_bdef, out, obaseT + WW);
}

extern "C" void kernel_launch(void* const* d_in, const int* in_sizes, int n_in,
                              void* d_out, int out_size)
{
    const float* x     = (const float*)d_in[0];
    const float* w_off = (const float*)d_in[1];
    const float* b_off = (const float*)d_in[2];
    const float* w_def = (const float*)d_in[3];
    const float* b_def = (const float*)d_in[4];
    float* out = (float*)d_out;

    const int totalQuads = 8 * 256 * 256;   // 524,288 2x2 quads
    const int threads = 128;
    const int blocks = totalQuads / threads; // 4096

    dcn_fused4_kernel<<<blocks, threads>>>(x, w_off, b_off, w_def, b_def, out);
}

// round 6
// speedup vs baseline: 1.5329x; 1.5329x over previous
#include <cuda_runtime.h>
#include <cuda_bf16.h>

// Fused DCNv2 forward, 2 pixels/thread, packed f32x2 math,
// all weights in __constant__ memory (uniform LDCU path, off the L1 crossbar).
//
//   ow   = conv3x3(x; w_off, b_off)            -> 27 channels per pixel
//   off  = ow[0:18]  (K=9 points, (y,x) pairs)
//   mask = sigmoid(ow[18:27])
//   out[o] = b_def[o] + sum_{c,k} w_def[o,c,k] * bilinear(x[c], p_k) * mask[k]
//
// x (8,3,512,512) f32, w_off (27,3,3,3), b_off (27), w_def (3,3,3,3), b_def (3).

#define HH 512
#define WW 512
#define CC 3
#define OCC 27
#define KK 9
#define HW (HH * WW)

typedef unsigned long long u64;

// Duplicated {w,w} weight pairs, transposed for the conv inner loop:
//   c_wd[g * 27 + oc] = {w_off[oc][g], w_off[oc][g]},  g = c*9 + ky*3 + kx
__constant__ u64  c_wd[OCC * 27];     // 5832 B
__constant__ u64  c_wdd[3 * 27];      // duplicated w_def, [o*27 + c*9 + k]
__constant__ float c_boff[OCC];
__constant__ float c_bdef[3];

// Device scratch the prep kernel writes; copied into __constant__ via D2D memcpy.
__device__ u64 g_wscratch[OCC * 27 + 3 * 27];

__device__ __forceinline__ u64 pk2(float lo, float hi) {
    u64 r; asm("mov.b64 %0, {%1, %2};" : "=l"(r) : "f"(lo), "f"(hi)); return r;
}
__device__ __forceinline__ void upk2(u64 v, float& lo, float& hi) {
    asm("mov.b64 {%0, %1}, %2;" : "=f"(lo), "=f"(hi) : "l"(v));
}
__device__ __forceinline__ void ffma2(u64& acc, u64 a, u64 b) {
    asm("fma.rn.f32x2 %0, %1, %2, %0;" : "+l"(acc) : "l"(a), "l"(b));
}

__global__ void dcn_prep_kernel(const float* __restrict__ w_off,
                                const float* __restrict__ w_def)
{
    const int i = threadIdx.x;
    if (i < OCC * 27) {
        const int g = i / OCC, oc = i % OCC;      // scratch[g*27+oc]
        const float w = w_off[oc * 27 + g];
        g_wscratch[g * 27 + oc] = pk2(w, w);
    }
    const int j = i - OCC * 27;
    if (j >= 0 && j < 3 * 27) {
        const float w = w_def[j];
        g_wscratch[OCC * 27 + j] = pk2(w, w);
    }
}

__global__ __launch_bounds__(128)
void dcn_fused2c_kernel(const float* __restrict__ x,
                        float* __restrict__ out)
{
    // One thread = pixel pair (hI, wI) and (hI, wI+1), wI even.
    const int idx = blockIdx.x * blockDim.x + threadIdx.x;   // 0 .. 8*512*256-1
    const int wI = (idx & 255) << 1;
    const int hI = (idx >> 8) & (HH - 1);
    const int b  = idx >> 17;

    const float* xb = x + (size_t)b * CC * HW;

    // ---- offset/mask conv on both pixels (packed) ----
    u64 ow[OCC];
#pragma unroll
    for (int oc = 0; oc < OCC; ++oc) {
        const float bv = c_boff[oc];
        ow[oc] = pk2(bv, bv);
    }

#pragma unroll
    for (int c = 0; c < CC; ++c) {
        const float* xc = xb + c * HW;
        // 3x4 window covering both pixels' 3x3 neighborhoods (zero padded)
        float win[12];
#pragma unroll
        for (int r = 0; r < 3; ++r) {
            const int y = hI + r - 1;
            const bool yv = ((unsigned)y < (unsigned)HH);
#pragma unroll
            for (int j = 0; j < 4; ++j) {
                const int xx = wI + j - 1;
                const bool v = yv && ((unsigned)xx < (unsigned)WW);
                win[r * 4 + j] = v ? __ldg(xc + y * WW + xx) : 0.0f;
            }
        }
#pragma unroll
        for (int t = 0; t < 9; ++t) {
            const int ky = t / 3, kx = t % 3;
            const u64 v2 = pk2(win[ky * 4 + kx], win[ky * 4 + kx + 1]);
            const int gbase = (c * 9 + t) * 27;   // compile-time after unroll
#pragma unroll
            for (int oc = 0; oc < OCC; ++oc)
                ffma2(ow[oc], c_wd[gbase + oc], v2);
        }
    }

    // ---- deformable sampling + channel mix (acc packed across the 2 pixels) ----
    u64 acc[3];
#pragma unroll
    for (int o = 0; o < 3; ++o) {
        const float bv = c_bdef[o];
        acc[o] = pk2(bv, bv);
    }

#pragma unroll
    for (int k = 0; k < KK; ++k) {
        float oy0, oy1, ox0, ox1, z0, z1;
        upk2(ow[2 * k],     oy0, oy1);
        upk2(ow[2 * k + 1], ox0, ox1);
        upk2(ow[18 + k],    z0,  z1);
        const float m0 = __fdividef(1.0f, 1.0f + __expf(-z0));
        const float m1 = __fdividef(1.0f, 1.0f + __expf(-z1));

        const float kyf = (float)(k / 3 - 1);
        const float kxf = (float)(k % 3 - 1);

        float w00[2], w01[2], w10[2], w11[2];
        int   i00[2];
        bool  y0v[2], y1v[2], x0v[2], x1v[2];
#pragma unroll
        for (int p = 0; p < 2; ++p) {
            const float py = (float)hI + kyf + (p ? oy1 : oy0);
            const float px = (float)(wI + p) + kxf + (p ? ox1 : ox0);
            const float y0f = floorf(py);
            const float x0f = floorf(px);
            const float dy = py - y0f;
            const float dx = px - x0f;
            const int y0 = (int)y0f;
            const int x0 = (int)x0f;
            w00[p] = (1.0f - dy) * (1.0f - dx);
            w01[p] = (1.0f - dy) * dx;
            w10[p] = dy * (1.0f - dx);
            w11[p] = dy * dx;
            y0v[p] = ((unsigned)y0       < (unsigned)HH);
            y1v[p] = ((unsigned)(y0 + 1) < (unsigned)HH);
            x0v[p] = ((unsigned)x0       < (unsigned)WW);
            x1v[p] = ((unsigned)(x0 + 1) < (unsigned)WW);
            i00[p] = y0 * WW + x0;
        }

#pragma unroll
        for (int c = 0; c < CC; ++c) {
            const float* pc = xb + c * HW;
            float val[2];
#pragma unroll
            for (int p = 0; p < 2; ++p) {
                const float v00 = (y0v[p] && x0v[p]) ? __ldg(pc + i00[p])          : 0.0f;
                const float v01 = (y0v[p] && x1v[p]) ? __ldg(pc + i00[p] + 1)      : 0.0f;
                const float v10 = (y1v[p] && x0v[p]) ? __ldg(pc + i00[p] + WW)     : 0.0f;
                const float v11 = (y1v[p] && x1v[p]) ? __ldg(pc + i00[p] + WW + 1) : 0.0f;
                val[p] = v00 * w00[p] + v01 * w01[p] + v10 * w10[p] + v11 * w11[p];
            }
            const u64 vp = pk2(val[0] * m0, val[1] * m1);
#pragma unroll
            for (int o = 0; o < 3; ++o)
                ffma2(acc[o], c_wdd[o * 27 + c * 9 + k], vp);
        }
    }

    const size_t obase = (size_t)b * 3 * HW + (size_t)hI * WW + wI;
#pragma unroll
    for (int o = 0; o < 3; ++o) {
        float lo, hi; upk2(acc[o], lo, hi);
        *reinterpret_cast<float2*>(out + obase + (size_t)o * HW) = make_float2(lo, hi);
    }
}

extern "C" void kernel_launch(void* const* d_in, const int* in_sizes, int n_in,
                              void* d_out, int out_size)
{
    const float* x     = (const float*)d_in[0];
    const float* w_off = (const float*)d_in[1];
    const float* b_off = (const float*)d_in[2];
    const float* w_def = (const float*)d_in[3];
    const float* b_def = (const float*)d_in[4];
    float* out = (float*)d_out;

    // 1) Build duplicated weight pairs in device scratch.
    dcn_prep_kernel<<<1, 1024>>>(w_off, w_def);

    // 2) Stage into __constant__ (device-to-device async copies; graph-capturable).
    void* scratch_ptr = nullptr;
    cudaGetSymbolAddress(&scratch_ptr, g_wscratch);
    cudaMemcpyToSymbolAsync(c_wd,  scratch_ptr, OCC * 27 * sizeof(u64), 0,
                            cudaMemcpyDeviceToDevice);
    cudaMemcpyToSymbolAsync(c_wdd, (const char*)scratch_ptr + OCC * 27 * sizeof(u64),
                            3 * 27 * sizeof(u64), 0, cudaMemcpyDeviceToDevice);
    cudaMemcpyToSymbolAsync(c_boff, b_off, OCC * sizeof(float), 0,
                            cudaMemcpyDeviceToDevice);
    cudaMemcpyToSymbolAsync(c_bdef, b_def, 3 * sizeof(float), 0,
                            cudaMemcpyDeviceToDevice);

    // 3) Main fused kernel.
    const int totalPairs = 8 * 512 * 256;    // 1,048,576 pixel pairs
    const int threads = 128;
    const int blocks = totalPairs / threads; // 8192
    dcn_fused2c_kernel<<<blocks, threads>>>(x, out);
}

// round 7
// speedup vs baseline: 1.7736x; 1.1570x over previous
#include <cuda_runtime.h>
#include <cuda_bf16.h>

// Fused DCNv2 forward, 2 pixels/thread, packed f32x2 math,
// all weights in one __constant__ blob (uniform LDCU path),
// staged by one prep kernel + one D2D memcpy.

#define HH 512
#define WW 512
#define CC 3
#define OCC 27
#define KK 9
#define HW (HH * WW)

typedef unsigned long long u64;

struct WConst {
    u64   wd[OCC * 27];   // duplicated {w,w}, transposed: wd[g*27+oc], g=c*9+ky*3+kx
    u64   wdd[3 * 27];    // duplicated w_def [o*27 + c*9 + k]
    float boff[28];       // padded
    float bdef[4];        // padded
};

__constant__ WConst c_w;
__device__   WConst g_scratch;

__device__ __forceinline__ u64 pk2(float lo, float hi) {
    u64 r; asm("mov.b64 %0, {%1, %2};" : "=l"(r) : "f"(lo), "f"(hi)); return r;
}
__device__ __forceinline__ void upk2(u64 v, float& lo, float& hi) {
    asm("mov.b64 {%0, %1}, %2;" : "=f"(lo), "=f"(hi) : "l"(v));
}
__device__ __forceinline__ void ffma2(u64& acc, u64 a, u64 b) {
    asm("fma.rn.f32x2 %0, %1, %2, %0;" : "+l"(acc) : "l"(a), "l"(b));
}

__global__ void dcn_prep_kernel(const float* __restrict__ w_off,
                                const float* __restrict__ b_off,
                                const float* __restrict__ w_def,
                                const float* __restrict__ b_def)
{
    const int i = threadIdx.x;
    if (i < OCC * 27) {                       // 729
        const int g = i / OCC, oc = i % OCC;
        const float w = w_off[oc * 27 + g];
        g_scratch.wd[g * 27 + oc] = pk2(w, w);
    } else if (i < OCC * 27 + 81) {           // 81
        const int j = i - OCC * 27;
        const float w = w_def[j];
        g_scratch.wdd[j] = pk2(w, w);
    } else if (i < OCC * 27 + 81 + 28) {      // 28
        const int j = i - (OCC * 27 + 81);
        g_scratch.boff[j] = (j < OCC) ? b_off[j] : 0.0f;
    } else if (i < OCC * 27 + 81 + 32) {      // 4
        const int j = i - (OCC * 27 + 81 + 28);
        g_scratch.bdef[j] = (j < 3) ? b_def[j] : 0.0f;
    }
}

__global__ __launch_bounds__(128, 5)
void dcn_fused2c_kernel(const float* __restrict__ x,
                        float* __restrict__ out)
{
    // One thread = pixel pair (hI, wI), (hI, wI+1) with wI even.
    const int idx = blockIdx.x * blockDim.x + threadIdx.x;   // 0 .. 8*512*256-1
    const int wI = (idx & 255) << 1;
    const int hI = (idx >> 8) & (HH - 1);
    const int b  = idx >> 17;

    const float* xb = x + (size_t)b * CC * HW;

    // ---- offset/mask conv on both pixels (packed) ----
    u64 ow[OCC];
#pragma unroll
    for (int oc = 0; oc < OCC; ++oc) {
        const float bv = c_w.boff[oc];
        ow[oc] = pk2(bv, bv);
    }

#pragma unroll
    for (int c = 0; c < CC; ++c) {
        const float* xc = xb + c * HW;
        // 3x4 window covering both pixels' 3x3 neighborhoods (zero padded).
        // Middle two columns (wI, wI+1) are 8B-aligned -> one LDG.64 per row.
        float win[12];
#pragma unroll
        for (int r = 0; r < 3; ++r) {
            const int y = hI + r - 1;
            const bool yv = ((unsigned)y < (unsigned)HH);
            const float* rowp = xc + y * WW;
            float2 mid = make_float2(0.0f, 0.0f);
            if (yv) mid = __ldg(reinterpret_cast<const float2*>(rowp + wI));
            win[r * 4 + 1] = mid.x;
            win[r * 4 + 2] = mid.y;
            win[r * 4 + 0] = (yv && wI > 0)        ? __ldg(rowp + wI - 1) : 0.0f;
            win[r * 4 + 3] = (yv && wI + 2 < WW)   ? __ldg(rowp + wI + 2) : 0.0f;
        }
#pragma unroll
        for (int t = 0; t < 9; ++t) {
            const int ky = t / 3, kx = t % 3;
            const u64 v2 = pk2(win[ky * 4 + kx], win[ky * 4 + kx + 1]);
            const int gbase = (c * 9 + t) * 27;   // compile-time after unroll
#pragma unroll
            for (int oc = 0; oc < OCC; ++oc)
                ffma2(ow[oc], c_w.wd[gbase + oc], v2);
        }
    }

    // ---- deformable sampling + channel mix (packed across the 2 pixels) ----
    u64 acc[3];
#pragma unroll
    for (int o = 0; o < 3; ++o) {
        const float bv = c_w.bdef[o];
        acc[o] = pk2(bv, bv);
    }

#pragma unroll
    for (int k = 0; k < KK; ++k) {
        float oy0, oy1, ox0, ox1, z0, z1;
        upk2(ow[2 * k],     oy0, oy1);
        upk2(ow[2 * k + 1], ox0, ox1);
        upk2(ow[18 + k],    z0,  z1);
        const float m0 = __fdividef(1.0f, 1.0f + __expf(-z0));
        const float m1 = __fdividef(1.0f, 1.0f + __expf(-z1));

        const float kyf = (float)(k / 3 - 1);
        const float kxf = (float)(k % 3 - 1);

        float w00[2], w01[2], w10[2], w11[2];
        int   i00[2];
        bool  y0v[2], y1v[2], x0v[2], x1v[2];
#pragma unroll
        for (int p = 0; p < 2; ++p) {
            const float py = (float)hI + kyf + (p ? oy1 : oy0);
            const float px = (float)(wI + p) + kxf + (p ? ox1 : ox0);
            const float y0f = floorf(py);
            const float x0f = floorf(px);
            const float dy = py - y0f;
            const float dx = px - x0f;
            const int y0 = (int)y0f;
            const int x0 = (int)x0f;
            w00[p] = (1.0f - dy) * (1.0f - dx);
            w01[p] = (1.0f - dy) * dx;
            w10[p] = dy * (1.0f - dx);
            w11[p] = dy * dx;
            y0v[p] = ((unsigned)y0       < (unsigned)HH);
            y1v[p] = ((unsigned)(y0 + 1) < (unsigned)HH);
            x0v[p] = ((unsigned)x0       < (unsigned)WW);
            x1v[p] = ((unsigned)(x0 + 1) < (unsigned)WW);
            i00[p] = y0 * WW + x0;
        }

#pragma unroll
        for (int c = 0; c < CC; ++c) {
            const float* pc = xb + c * HW;
            float val[2];
#pragma unroll
            for (int p = 0; p < 2; ++p) {
                const float v00 = (y0v[p] && x0v[p]) ? __ldg(pc + i00[p])          : 0.0f;
                const float v01 = (y0v[p] && x1v[p]) ? __ldg(pc + i00[p] + 1)      : 0.0f;
                const float v10 = (y1v[p] && x0v[p]) ? __ldg(pc + i00[p] + WW)     : 0.0f;
                const float v11 = (y1v[p] && x1v[p]) ? __ldg(pc + i00[p] + WW + 1) : 0.0f;
                val[p] = v00 * w00[p] + v01 * w01[p] + v10 * w10[p] + v11 * w11[p];
            }
            const u64 vp = pk2(val[0] * m0, val[1] * m1);
#pragma unroll
            for (int o = 0; o < 3; ++o)
                ffma2(acc[o], c_w.wdd[o * 27 + c * 9 + k], vp);
        }
    }

    const size_t obase = (size_t)b * 3 * HW + (size_t)hI * WW + wI;
#pragma unroll
    for (int o = 0; o < 3; ++o) {
        float lo, hi; upk2(acc[o], lo, hi);
        *reinterpret_cast<float2*>(out + obase + (size_t)o * HW) = make_float2(lo, hi);
    }
}

extern "C" void kernel_launch(void* const* d_in, const int* in_sizes, int n_in,
                              void* d_out, int out_size)
{
    const float* x     = (const float*)d_in[0];
    const float* w_off = (const float*)d_in[1];
    const float* b_off = (const float*)d_in[2];
    const float* w_def = (const float*)d_in[3];
    const float* b_def = (const float*)d_in[4];
    float* out = (float*)d_out;

    // 1) Build duplicated weight pairs + biases in device scratch (one block).
    dcn_prep_kernel<<<1, 896>>>(w_off, b_off, w_def, b_def);

    // 2) Stage the whole blob into __constant__ with ONE D2D copy.
    void* scratch_ptr = nullptr;
    cudaGetSymbolAddress(&scratch_ptr, g_scratch);
    cudaMemcpyToSymbolAsync(c_w, scratch_ptr, sizeof(WConst), 0,
                            cudaMemcpyDeviceToDevice);

    // 3) Main fused kernel.
    const int totalPairs = 8 * 512 * 256;    // 1,048,576 pixel pairs
    const int threads = 128;
    const int blocks = totalPairs / threads; // 8192
    dcn_fused2c_kernel<<<blocks, threads>>>(x, out);
}